// round 1
// baseline (speedup 1.0000x reference)
#include <cuda_runtime.h>
#include <cuda_bf16.h>

// Net_5437428596910: single-lane LSTM recurrence, H=10, T = seq*batch = 65536.
// out = last 64 hidden states -> [64,1,10] float32 (640 elems).
//
// Kernel 1 (parallel): xp[t][j] = float4(i,f,g,o) pre-activations from input path.
// Kernel 2 (1 warp, sequential): 65536-step scan, lanes 0..9 own hidden units.

#define H 10
#define MAXT 65536

// Scratch: permuted input projections, padded by 8 steps for prefetch overrun.
__device__ float4 g_xp4[(MAXT + 8) * H];

__global__ void xproj_kernel(const float* __restrict__ x,
                             const float* __restrict__ w_ih,
                             const float* __restrict__ b_ih,
                             const float* __restrict__ b_hh,
                             int T) {
    int idx = blockIdx.x * blockDim.x + threadIdx.x;  // one thread per (t, j)
    if (idx >= T * H) return;
    int t = idx / H;
    int j = idx - t * H;

    float xr[H];
#pragma unroll
    for (int k = 0; k < H; k++) xr[k] = __ldg(x + t * H + k);

    float acc[4];
#pragma unroll
    for (int g = 0; g < 4; g++) {
        int row = g * H + j;                 // PyTorch gate order: i, f, g, o
        float a = __ldg(b_ih + row) + __ldg(b_hh + row);
#pragma unroll
        for (int k = 0; k < H; k++)
            a = fmaf(xr[k], __ldg(w_ih + row * H + k), a);
        acc[g] = a;
    }
    g_xp4[idx] = make_float4(acc[0], acc[1], acc[2], acc[3]);
}

__device__ __forceinline__ float sigmoid_f(float x) {
    // 1/(1+e^-x); __expf(-x)->inf for very negative x gives 0, ->0 gives 1. Safe.
    return __fdividef(1.0f, 1.0f + __expf(-x));
}

__device__ __forceinline__ float tanh_f(float x) {
    // tanh(|x|) = (1-e)/(1+e), e = exp(-2|x|) in [0,1] -> no overflow; restore sign.
    float e = __expf(-2.0f * fabsf(x));
    float r = __fdividef(1.0f - e, 1.0f + e);
    return copysignf(r, x);
}

__device__ __forceinline__ void lstm_step(float4 a, const float (&W)[4][H],
                                          float& h, float& c) {
    float hk[H];
#pragma unroll
    for (int k = 0; k < H; k++) hk[k] = __shfl_sync(0xffffffffu, h, k);

    float ai = a.x, af = a.y, ag = a.z, ao = a.w;
#pragma unroll
    for (int k = 0; k < H; k++) {
        ai = fmaf(hk[k], W[0][k], ai);
        af = fmaf(hk[k], W[1][k], af);
        ag = fmaf(hk[k], W[2][k], ag);
        ao = fmaf(hk[k], W[3][k], ao);
    }
    float ig = sigmoid_f(ai);
    float fg = sigmoid_f(af);
    float gg = tanh_f(ag);
    float og = sigmoid_f(ao);
    c = fmaf(fg, c, ig * gg);
    h = og * tanh_f(c);
}

__global__ void __launch_bounds__(32, 1)
scan_kernel(const float* __restrict__ w_hh,
            const float* __restrict__ h0,
            const float* __restrict__ c0,
            float* __restrict__ out,
            int T) {
    int lane = threadIdx.x;
    int j = lane < H ? lane : 0;  // lanes >= H do harmless redundant work

    // Recurrent weights for this unit's 4 gates: 40 regs.
    float W[4][H];
#pragma unroll
    for (int g = 0; g < 4; g++)
#pragma unroll
        for (int k = 0; k < H; k++)
            W[g][k] = w_hh[(g * H + j) * H + k];

    float h = h0[j];
    float c = c0[j];

    // 4-step register prefetch ring: loads ~700 cy ahead, hides L2 (~250 cy).
    float4 buf[4];
#pragma unroll
    for (int u = 0; u < 4; u++) buf[u] = g_xp4[u * H + j];

    int Tm = T - 64;  // 65472, divisible by 4

    // Hot loop: no output stores, no per-step predication.
    for (int t0 = 0; t0 < Tm; t0 += 4) {
        float4 nxt[4];
#pragma unroll
        for (int u = 0; u < 4; u++) nxt[u] = g_xp4[(t0 + 4 + u) * H + j];
#pragma unroll
        for (int u = 0; u < 4; u++) lstm_step(buf[u], W, h, c);
#pragma unroll
        for (int u = 0; u < 4; u++) buf[u] = nxt[u];
    }

    // Tail: last 64 steps, store h each step.
    for (int t0 = Tm; t0 < T; t0 += 4) {
        float4 nxt[4];
#pragma unroll
        for (int u = 0; u < 4; u++) nxt[u] = g_xp4[(t0 + 4 + u) * H + j];
#pragma unroll
        for (int u = 0; u < 4; u++) {
            lstm_step(buf[u], W, h, c);
            if (lane < H) out[(t0 + u - Tm) * H + j] = h;
        }
#pragma unroll
        for (int u = 0; u < 4; u++) buf[u] = nxt[u];
    }
}

extern "C" void kernel_launch(void* const* d_in, const int* in_sizes, int n_in,
                              void* d_out, int out_size) {
    const float* x    = (const float*)d_in[0];
    const float* w_ih = (const float*)d_in[1];
    const float* w_hh = (const float*)d_in[2];
    const float* b_ih = (const float*)d_in[3];
    const float* b_hh = (const float*)d_in[4];
    const float* h0   = (const float*)d_in[5];
    const float* c0   = (const float*)d_in[6];
    float* out = (float*)d_out;

    int T = in_sizes[0] / H;  // 65536
    if (T > MAXT) T = MAXT;

    int nthreads = T * H;
    xproj_kernel<<<(nthreads + 255) / 256, 256>>>(x, w_ih, b_ih, b_hh, T);
    scan_kernel<<<1, 32>>>(w_hh, h0, c0, out, T);
}

// round 2
// speedup vs baseline: 1.5213x; 1.5213x over previous
#include <cuda_runtime.h>
#include <cuda_bf16.h>

// Net_5437428596910: single-lane LSTM recurrence, H=10, T = seq*batch = 65536.
// R2: f32x2 packed recurrent GEMV (gate pairs (i,f) and (g,o) per lane),
//     split accumulation trees, and HW tanh.approx activations
//     (sigmoid via 0.5 + 0.5*tanh(x/2)) -> 5 MUFU/step instead of 10,
//     ~44 FMA-pipe cy/step instead of 80.

#define H 10
#define MAXT 65536

typedef unsigned long long u64;

__device__ float4 g_xp4[(MAXT + 8) * H];

__global__ void xproj_kernel(const float* __restrict__ x,
                             const float* __restrict__ w_ih,
                             const float* __restrict__ b_ih,
                             const float* __restrict__ b_hh,
                             int T) {
    int idx = blockIdx.x * blockDim.x + threadIdx.x;  // one thread per (t, j)
    if (idx >= T * H) return;
    int t = idx / H;
    int j = idx - t * H;

    float xr[H];
#pragma unroll
    for (int k = 0; k < H; k++) xr[k] = __ldg(x + t * H + k);

    float acc[4];
#pragma unroll
    for (int g = 0; g < 4; g++) {
        int row = g * H + j;                 // PyTorch gate order: i, f, g, o
        float a = __ldg(b_ih + row) + __ldg(b_hh + row);
#pragma unroll
        for (int k = 0; k < H; k++)
            a = fmaf(xr[k], __ldg(w_ih + row * H + k), a);
        acc[g] = a;
    }
    g_xp4[idx] = make_float4(acc[0], acc[1], acc[2], acc[3]);
}

// ---- f32x2 helpers (sm_103a packed-pair FMA path, PTX-only) ----
__device__ __forceinline__ u64 pk2(float lo, float hi) {
    u64 r; asm("mov.b64 %0, {%1, %2};" : "=l"(r) : "f"(lo), "f"(hi)); return r;
}
__device__ __forceinline__ void upk2(u64 v, float& lo, float& hi) {
    asm("mov.b64 {%0, %1}, %2;" : "=f"(lo), "=f"(hi) : "l"(v));
}
__device__ __forceinline__ u64 fma2(u64 a, u64 b, u64 c) {
    u64 d; asm("fma.rn.f32x2 %0, %1, %2, %3;" : "=l"(d) : "l"(a), "l"(b), "l"(c));
    return d;
}
__device__ __forceinline__ u64 mul2(u64 a, u64 b) {
    u64 d; asm("mul.rn.f32x2 %0, %1, %2;" : "=l"(d) : "l"(a), "l"(b));
    return d;
}
__device__ __forceinline__ u64 add2(u64 a, u64 b) {
    u64 d; asm("add.rn.f32x2 %0, %1, %2;" : "=l"(d) : "l"(a), "l"(b));
    return d;
}
__device__ __forceinline__ float tanh_hw(float x) {
    float y; asm("tanh.approx.f32 %0, %1;" : "=f"(y) : "f"(x)); return y;
}

// One LSTM step. Wif[k] = (W_i[j][k], W_f[j][k]); Wgo[k] = (W_g[j][k], W_o[j][k]).
__device__ __forceinline__ void lstm_step(float4 a, const u64 (&Wif)[H],
                                          const u64 (&Wgo)[H],
                                          float& h, float& c) {
    // Broadcast h vector; duplicate each h_k into both packed halves.
    u64 hp[H];
#pragma unroll
    for (int k = 0; k < H; k++) {
        float hk = __shfl_sync(0xffffffffu, h, k);
        hp[k] = pk2(hk, hk);
    }

    // Packed gate pre-activations, two 5-deep trees per pair.
    u64 aA = pk2(a.x, a.y);            // (i, f)
    u64 bA = pk2(a.z, a.w);            // (g, o)
    u64 aB = mul2(hp[5], Wif[5]);
    u64 bB = mul2(hp[5], Wgo[5]);
#pragma unroll
    for (int k = 0; k < 5; k++) {
        aA = fma2(hp[k], Wif[k], aA);
        bA = fma2(hp[k], Wgo[k], bA);
    }
#pragma unroll
    for (int k = 6; k < H; k++) {
        aB = fma2(hp[k], Wif[k], aB);
        bB = fma2(hp[k], Wgo[k], bB);
    }
    aA = add2(aA, aB);
    bA = add2(bA, bB);

    float ai, af, ag, ao;
    upk2(aA, ai, af);
    upk2(bA, ag, ao);

    // sigmoid(x) = 0.5 + 0.5 * tanh(0.5 x); g uses tanh directly.
    // Issue order: i, f, g first (they gate c), o last.
    float ti = tanh_hw(0.5f * ai);
    float tf = tanh_hw(0.5f * af);
    float tg = tanh_hw(ag);
    float to = tanh_hw(0.5f * ao);
    float ig = fmaf(0.5f, ti, 0.5f);
    float fg = fmaf(0.5f, tf, 0.5f);
    float og = fmaf(0.5f, to, 0.5f);
    c = fmaf(fg, c, ig * tg);
    h = og * tanh_hw(c);
}

__global__ void __launch_bounds__(32, 1)
scan_kernel(const float* __restrict__ w_hh,
            const float* __restrict__ h0,
            const float* __restrict__ c0,
            float* __restrict__ out,
            int T) {
    int lane = threadIdx.x;
    int j = lane < H ? lane : 0;  // lanes >= H do harmless redundant work

    // Packed recurrent weights for this unit: (i,f) and (g,o) pairs.
    u64 Wif[H], Wgo[H];
#pragma unroll
    for (int k = 0; k < H; k++) {
        Wif[k] = pk2(w_hh[(0 * H + j) * H + k], w_hh[(1 * H + j) * H + k]);
        Wgo[k] = pk2(w_hh[(2 * H + j) * H + k], w_hh[(3 * H + j) * H + k]);
    }

    float h = h0[j];
    float c = c0[j];

    // 4-step register prefetch ring: loads ~500+ cy ahead, hides L2 latency.
    float4 buf[4];
#pragma unroll
    for (int u = 0; u < 4; u++) buf[u] = g_xp4[u * H + j];

    int Tm = T - 64;  // 65472, divisible by 4

    // Hot loop: no output stores, no per-step predication.
    for (int t0 = 0; t0 < Tm; t0 += 4) {
        float4 nxt[4];
#pragma unroll
        for (int u = 0; u < 4; u++) nxt[u] = g_xp4[(t0 + 4 + u) * H + j];
#pragma unroll
        for (int u = 0; u < 4; u++) lstm_step(buf[u], Wif, Wgo, h, c);
#pragma unroll
        for (int u = 0; u < 4; u++) buf[u] = nxt[u];
    }

    // Tail: last 64 steps, store h each step.
    for (int t0 = Tm; t0 < T; t0 += 4) {
        float4 nxt[4];
#pragma unroll
        for (int u = 0; u < 4; u++) nxt[u] = g_xp4[(t0 + 4 + u) * H + j];
#pragma unroll
        for (int u = 0; u < 4; u++) {
            lstm_step(buf[u], Wif, Wgo, h, c);
            if (lane < H) out[(t0 + u - Tm) * H + j] = h;
        }
#pragma unroll
        for (int u = 0; u < 4; u++) buf[u] = nxt[u];
    }
}

extern "C" void kernel_launch(void* const* d_in, const int* in_sizes, int n_in,
                              void* d_out, int out_size) {
    const float* x    = (const float*)d_in[0];
    const float* w_ih = (const float*)d_in[1];
    const float* w_hh = (const float*)d_in[2];
    const float* b_ih = (const float*)d_in[3];
    const float* b_hh = (const float*)d_in[4];
    const float* h0   = (const float*)d_in[5];
    const float* c0   = (const float*)d_in[6];
    float* out = (float*)d_out;

    int T = in_sizes[0] / H;  // 65536
    if (T > MAXT) T = MAXT;

    int nthreads = T * H;
    xproj_kernel<<<(nthreads + 255) / 256, 256>>>(x, w_ih, b_ih, b_hh, T);
    scan_kernel<<<1, 32>>>(w_hh, h0, c0, out, T);
}